// round 6
// baseline (speedup 1.0000x reference)
#include <cuda_runtime.h>
#include <math.h>

#define N_ROWS 8192
#define N_COLS 512
#define GRID_A 256
#define THREADS_A 512
#define WARPS_A 16             /* 256 blocks * 16 warps * 2 rows = 8192 rows */
#define NREP 8                 /* column-accumulator replicas */

#define SCALE_D   4294967296.0          /* 2^32 */
#define INV_SCALE (1.0 / 4294967296.0)

// Order-invariant integer accumulators (zero-init; last block resets).
__device__ unsigned long long g_col_ll[NREP][N_COLS];
__device__ unsigned long long g_S_ll;
__device__ int g_max_int;               // bit-cast float, values >= 0
__device__ unsigned int g_counter;

__global__ void __launch_bounds__(THREADS_A, 2)
fused_loss_kernel(const float* __restrict__ x, float* __restrict__ out) {
    __shared__ float s_colw[WARPS_A][N_COLS];   // 32 KB
    __shared__ float s_S[WARPS_A];
    __shared__ float s_M[WARPS_A];
    __shared__ double s_red[THREADS_A];         // 4 KB
    __shared__ unsigned int s_last;

    const int tid = threadIdx.x;
    const int wid = tid >> 5;
    const int lid = tid & 31;

    // ---- streaming: warp owns 2 rows; 8 named float4 loads, all up front ----
    const int row0 = (blockIdx.x * WARPS_A + wid) * 2;
    const float4* p0 = reinterpret_cast<const float4*>(x + (size_t)row0 * N_COLS);
    const float4* p1 = reinterpret_cast<const float4*>(x + (size_t)(row0 + 1) * N_COLS);

    const float4 a0 = p0[lid];
    const float4 a1 = p0[32 + lid];
    const float4 a2 = p0[64 + lid];
    const float4 a3 = p0[96 + lid];
    const float4 b0 = p1[lid];
    const float4 b1 = p1[32 + lid];
    const float4 b2 = p1[64 + lid];
    const float4 b3 = p1[96 + lid];

    // column partials into smem (vectorized, conflict-free)
    float4 c0, c1, c2, c3;
    c0.x = a0.x + b0.x; c0.y = a0.y + b0.y; c0.z = a0.z + b0.z; c0.w = a0.w + b0.w;
    c1.x = a1.x + b1.x; c1.y = a1.y + b1.y; c1.z = a1.z + b1.z; c1.w = a1.w + b1.w;
    c2.x = a2.x + b2.x; c2.y = a2.y + b2.y; c2.z = a2.z + b2.z; c2.w = a2.w + b2.w;
    c3.x = a3.x + b3.x; c3.y = a3.y + b3.y; c3.z = a3.z + b3.z; c3.w = a3.w + b3.w;
    *reinterpret_cast<float4*>(&s_colw[wid][0   + lid * 4]) = c0;
    *reinterpret_cast<float4*>(&s_colw[wid][128 + lid * 4]) = c1;
    *reinterpret_cast<float4*>(&s_colw[wid][256 + lid * 4]) = c2;
    *reinterpret_cast<float4*>(&s_colw[wid][384 + lid * 4]) = c3;

    float sq0 = a0.x * a0.x + a0.y * a0.y + a0.z * a0.z + a0.w * a0.w
              + a1.x * a1.x + a1.y * a1.y + a1.z * a1.z + a1.w * a1.w
              + a2.x * a2.x + a2.y * a2.y + a2.z * a2.z + a2.w * a2.w
              + a3.x * a3.x + a3.y * a3.y + a3.z * a3.z + a3.w * a3.w;
    float sq1 = b0.x * b0.x + b0.y * b0.y + b0.z * b0.z + b0.w * b0.w
              + b1.x * b1.x + b1.y * b1.y + b1.z * b1.z + b1.w * b1.w
              + b2.x * b2.x + b2.y * b2.y + b2.z * b2.z + b2.w * b2.w
              + b3.x * b3.x + b3.y * b3.y + b3.z * b3.z + b3.w * b3.w;

    // warp-reduce both row norms
    #pragma unroll
    for (int off = 16; off > 0; off >>= 1) {
        sq0 += __shfl_xor_sync(0xffffffffu, sq0, off);
        sq1 += __shfl_xor_sync(0xffffffffu, sq1, off);
    }
    if (lid == 0) {
        s_S[wid] = sq0 + sq1;
        s_M[wid] = fmaxf(sq0, sq1);
    }
    __syncthreads();

    // ---- block epilogue: one column per thread, push int64 atomics ----
    const int rep = blockIdx.x & (NREP - 1);
    {
        float v = 0.f;
        #pragma unroll
        for (int w = 0; w < WARPS_A; ++w) v += s_colw[w][tid];
        const long long q = __double2ll_rn((double)v * SCALE_D);
        atomicAdd(&g_col_ll[rep][tid], (unsigned long long)q);
    }
    if (tid == 0) {
        float Sp = 0.f, Mp = 0.f;
        #pragma unroll
        for (int w = 0; w < WARPS_A; ++w) {
            Sp += s_S[w];
            Mp = fmaxf(Mp, s_M[w]);
        }
        atomicAdd(&g_S_ll, (unsigned long long)__double2ll_rn((double)Sp * SCALE_D));
        atomicMax(&g_max_int, __float_as_int(Mp));
        __threadfence();
        const unsigned int prev = atomicAdd(&g_counter, 1u);
        s_last = (prev == (unsigned int)(GRID_A - 1)) ? 1u : 0u;
    }
    __syncthreads();
    if (s_last == 0u) return;

    // ---- finalize: last block; accumulators are tiny and L2-hot ----
    __threadfence();

    long long t0 = 0ll;
    #pragma unroll
    for (int r = 0; r < NREP; ++r)
        t0 += (long long)g_col_ll[r][tid];
    const double d0 = (double)t0 * INV_SCALE;

    s_red[tid] = d0 * d0;
    __syncthreads();
    #pragma unroll
    for (int s = THREADS_A / 2; s > 0; s >>= 1) {
        if (tid < s) s_red[tid] += s_red[tid + s];
        __syncthreads();
    }
    // all reads of g_col_ll done (barrier above) -> safe to reset
    #pragma unroll
    for (int r = 0; r < NREP; ++r)
        g_col_ll[r][tid] = 0ull;

    if (tid == 0) {
        const double ssq_total = s_red[0];
        const double S_total = (double)(long long)g_S_ll * INV_SCALE;
        const double maxsq = (double)__int_as_float(g_max_int);
        const double numer = (double)N_ROWS * S_total - ssq_total;
        const double norm = sqrt(maxsq);
        const double count = (double)N_ROWS * (double)(N_ROWS - 1) * 0.5;
        out[0] = (float)(numer / (norm * count));
        // reset scalars for next graph replay
        g_S_ll = 0ull;
        g_max_int = 0;
        g_counter = 0u;
    }
}

extern "C" void kernel_launch(void* const* d_in, const int* in_sizes, int n_in,
                              void* d_out, int out_size) {
    (void)in_sizes; (void)n_in; (void)out_size;
    const float* x = (const float*)d_in[0];
    float* out = (float*)d_out;
    fused_loss_kernel<<<GRID_A, THREADS_A>>>(x, out);
}